// round 1
// baseline (speedup 1.0000x reference)
#include <cuda_runtime.h>
#include <math.h>

#define H      2048
#define NK     4
#define NITER  9
#define MAXSRC 11          // 0=x, 1=h, 2..10 = G[0..8]
#define MAXPAIR 64
#define MAXGROUPS 440      // C(11,2)*4*2
#define MAXENT   1760      // MAXGROUPS * 4
#define HCHUNK   8
#define GCHUNKS  8
#define GPERCHUNK 55

// ---------------- device state (no allocations allowed) ----------------
__device__ float g_PL[MAXSRC * NK * H];     // src @ L_k
__device__ float g_PR[MAXSRC * NK * H];     // src @ R_k
__device__ float g_G[NITER * H];
__device__ float g_groupsum[(size_t)MAXGROUPS * H];
__device__ float g_scores4[MAXGROUPS * 4];
__device__ int   g_aflag[MAXGROUPS];
__device__ float g_sumpart[GCHUNKS * H];
__device__ float g_projpart[(size_t)2 * 2 * NK * HCHUNK * H]; // [vec][mat][k][hc][d]
__device__ int   g_comp[16];
__device__ int   g_ncomp;

// ---------------- helpers ----------------
__device__ __forceinline__ int gen_pairs(int nc, int lc, int r,
                                         unsigned char* pi, unsigned char* pj) {
    int nri = NITER - r;
    int np = 0;
    for (int i = 0; i < nc - 1; i++)
        for (int j = i + 1; j < nc; j++) {
            bool flag;
            if (nri == lc - 1)      flag = (i >= 3);
            else if (nri == lc)     flag = (j >= 3);
            else                    flag = (nri > lc);
            if (flag) { pi[np] = (unsigned char)i; pj[np] = (unsigned char)j; np++; }
        }
    return np;
}

__device__ __forceinline__ int count_pairs(int nc, int lc, int r) {
    int nri = NITER - r;
    int np = 0;
    for (int i = 0; i < nc - 1; i++)
        for (int j = i + 1; j < nc; j++) {
            bool flag;
            if (nri == lc - 1)      flag = (i >= 3);
            else if (nri == lc)     flag = (j >= 3);
            else                    flag = (nri > lc);
            if (flag) np++;
        }
    return np;
}

__device__ __forceinline__ float blockRedSum(float v, float* s) {
    for (int o = 16; o; o >>= 1) v += __shfl_down_sync(0xffffffffu, v, o);
    int nw = blockDim.x >> 5;
    if ((threadIdx.x & 31) == 0) s[threadIdx.x >> 5] = v;
    __syncthreads();
    if (threadIdx.x == 0) {
        float r = s[0];
        for (int i = 1; i < nw; i++) r += s[i];
        s[0] = r;
    }
    __syncthreads();
    float r = s[0];
    __syncthreads();
    return r;
}

__device__ __forceinline__ float blockRedMax(float v, float* s) {
    for (int o = 16; o; o >>= 1) v = fmaxf(v, __shfl_down_sync(0xffffffffu, v, o));
    int nw = blockDim.x >> 5;
    if ((threadIdx.x & 31) == 0) s[threadIdx.x >> 5] = v;
    __syncthreads();
    if (threadIdx.x == 0) {
        float r = s[0];
        for (int i = 1; i < nw; i++) r = fmaxf(r, s[i]);
        s[0] = r;
    }
    __syncthreads();
    float r = s[0];
    __syncthreads();
    return r;
}

__device__ __forceinline__ void fma4(float4& a, float sc, const float4 m) {
    a.x = fmaf(sc, m.x, a.x);
    a.y = fmaf(sc, m.y, a.y);
    a.z = fmaf(sc, m.z, a.z);
    a.w = fmaf(sc, m.w, a.w);
}

// ---------------- kernels ----------------
__global__ void k_init() { if (threadIdx.x == 0) g_ncomp = 0; }

// Project vector(s) through all 4 L_k and R_k. Grid: 2mats*4k*2dblk*8hchunk = 128 blocks.
__global__ void __launch_bounds__(256) k_project(
    const float* __restrict__ L, const float* __restrict__ R,
    const float* __restrict__ xv, const float* __restrict__ hv, int gsrc)
{
    int bid = blockIdx.x;
    int hc   = bid & 7;  bid >>= 3;
    int dblk = bid & 1;  bid >>= 1;
    int k    = bid & 3;  bid >>= 2;
    int mat  = bid;
    const float* M = (mat == 0 ? L : R) + (size_t)k * H * H;
    const float* v0;
    const float* v1 = nullptr;
    if (gsrc >= 0) v0 = &g_G[(size_t)gsrc * H];
    else { v0 = xv; v1 = hv; }
    const bool dual = (v1 != nullptr);

    int col = dblk * 1024 + threadIdx.x * 4;
    int h0 = hc * (H / HCHUNK);
    float4 a0 = make_float4(0.f, 0.f, 0.f, 0.f);
    float4 a1 = make_float4(0.f, 0.f, 0.f, 0.f);
    for (int hh = h0; hh < h0 + (H / HCHUNK); hh += 4) {
#pragma unroll
        for (int u = 0; u < 4; u++) {
            float4 m = *reinterpret_cast<const float4*>(&M[(size_t)(hh + u) * H + col]);
            float va = __ldg(&v0[hh + u]);
            fma4(a0, va, m);
            if (dual) {
                float vb = __ldg(&v1[hh + u]);
                fma4(a1, vb, m);
            }
        }
    }
    size_t base0 = (((size_t)(0 * 2 + mat) * NK + k) * HCHUNK + hc) * H + col;
    *reinterpret_cast<float4*>(&g_projpart[base0]) = a0;
    if (dual) {
        size_t base1 = (((size_t)(1 * 2 + mat) * NK + k) * HCHUNK + hc) * H + col;
        *reinterpret_cast<float4*>(&g_projpart[base1]) = a1;
    }
}

__global__ void __launch_bounds__(256) k_projreduce(int src0, int nvec)
{
    int idx = blockIdx.x * 256 + threadIdx.x;
    int total = nvec * 2 * NK * H;
    if (idx >= total) return;
    int d = idx & (H - 1);
    int t = idx >> 11;
    int k = t & 3;   t >>= 2;
    int mat = t & 1; t >>= 1;
    int v = t;
    float s = 0.f;
#pragma unroll
    for (int hc = 0; hc < HCHUNK; hc++)
        s += g_projpart[(((size_t)(v * 2 + mat) * NK + k) * HCHUNK + hc) * H + d];
    float* dst = (mat == 0 ? g_PL : g_PR);
    dst[((size_t)(src0 + v) * NK + k) * H + d] = s;
}

// One block per (pair,k,bf) group: res, max|res|, 4 activation scores, group act-sum vector.
__global__ void __launch_bounds__(256) k_groups(
    const float* __restrict__ bv, const float* __restrict__ w, int r)
{
    __shared__ float s_res[H];
    __shared__ float s_s12[H];
    __shared__ unsigned char pi[MAXPAIR], pj[MAXPAIR];
    __shared__ int meta[6];
    __shared__ float sred[8];
    int tid = threadIdx.x;
    if (tid == 0) {
        int lc = g_ncomp, nc = 3 + lc;
        int np = gen_pairs(nc, lc, r, pi, pj);
        int g = blockIdx.x;
        if (g >= np * 8) meta[0] = 0;
        else {
            meta[0] = 1;
            int pidx = g >> 3, k = (g >> 1) & 3, bf = g & 1;
            int i = pi[pidx], j = pj[pidx];
            meta[1] = (i == 2) ? -1 : (i < 2 ? i : 2 + g_comp[i - 3]);
            meta[2] = (j == 2) ? -1 : (j < 2 ? j : 2 + g_comp[j - 3]);
            meta[3] = k; meta[4] = bf;
        }
    }
    __syncthreads();
    if (!meta[0]) return;
    int sa = meta[1], sbv = meta[2], k = meta[3], bf = meta[4];
    const float* pa = (sa  >= 0) ? &g_PL[(size_t)(sa  * NK + k) * H] : nullptr;
    const float* pb = (sbv >= 0) ? &g_PR[(size_t)(sbv * NK + k) * H] : nullptr;
    float am = 0.f, ds = 0.f, dt = 0.f, dm = 0.f, di = 0.f;
#pragma unroll
    for (int it = 0; it < H / 256; it++) {
        int d = tid + it * 256;
        float a = pa ? pa[d] : 0.f;
        float c = pb ? pb[d] : 0.f;
        float bb = bv[k * H + d];
        float res = bf ? (a + c + bb) : fmaf(a, c, bb);
        s_res[d] = res;
        am = fmaxf(am, fabsf(res));
        float wv = w[d];
        float sg = 0.001f / (1.f + expf(-res));
        float th = 0.001f * tanhf(res);
        s_s12[d] = sg + th;
        ds = fmaf(sg, wv, ds);
        dt = fmaf(th, wv, dt);
        dm = fmaf(1.f - res, wv, dm);
        di = fmaf(res, wv, di);
    }
    float m = blockRedMax(am, sred);
    ds = blockRedSum(ds, sred);
    dt = blockRedSum(dt, sred);
    dm = blockRedSum(dm, sred);
    di = blockRedSum(di, sred);
    int g = blockIdx.x;
    int na = (m >= 1.0f) ? 2 : 4;
    if (tid == 0) {
        g_aflag[g] = na;
        g_scores4[g * 4 + 0] = ds;
        g_scores4[g * 4 + 1] = dt;
        g_scores4[g * 4 + 2] = dm;
        g_scores4[g * 4 + 3] = di;
    }
#pragma unroll
    for (int it = 0; it < H / 256; it++) {
        int d = tid + it * 256;
        float res = s_res[d];
        float gs = s_s12[d];
        if (na == 4) gs += (1.f - res) + res;
        g_groupsum[(size_t)g * H + d] = gs;
    }
}

// Partial (deterministic) sum of group vectors: grid 8 gchunks x 8 dblocks.
__global__ void __launch_bounds__(256) k_sumvpart(int r)
{
    int gc = blockIdx.x >> 3;
    int db = blockIdx.x & 7;
    int d = db * 256 + threadIdx.x;
    int lc = g_ncomp, nc = 3 + lc;
    int ng = count_pairs(nc, lc, r) * 8;
    int g0 = gc * GPERCHUNK;
    int g1 = min(ng, g0 + GPERCHUNK);
    float s = 0.f;
    for (int g = g0; g < g1; g++) s += g_groupsum[(size_t)g * H + d];
    g_sumpart[gc * H + d] = s;
}

// Single-block: compact entries, argmax, softmax prob[nc-2], rank-of-entry-1 second,
// comp_src update, emit G[r] / dots / outputs.
__global__ void __launch_bounds__(1024) k_select_emit(
    const float* __restrict__ bv, const float* __restrict__ w,
    int r, float* __restrict__ out)
{
    __shared__ float ent_s[MAXENT];
    __shared__ unsigned short ent_g[MAXENT];
    __shared__ unsigned char ent_a[MAXENT];
    __shared__ unsigned char pi[MAXPAIR], pj[MAXPAIR];
    __shared__ int s_na[512];
    __shared__ int s_pref[512];
    __shared__ float sred[32];
    __shared__ int sredi[32];
    __shared__ int s_ng, s_nc;
    __shared__ float s_pnc;
    __shared__ int s_sec[5];

    int tid = threadIdx.x;
    if (tid == 0) {
        int lc = g_ncomp, nc = 3 + lc;
        int np = gen_pairs(nc, lc, r, pi, pj);
        s_ng = np * 8; s_nc = nc;
    }
    __syncthreads();
    int ng = s_ng, nc = s_nc;

    if (tid < 512) s_na[tid] = (tid < ng) ? g_aflag[tid] : 0;
    __syncthreads();
    if (tid < 512) s_pref[tid] = s_na[tid];
    __syncthreads();
    for (int off = 1; off < 512; off <<= 1) {
        int v = 0;
        if (tid < 512 && tid >= off) v = s_pref[tid - off];
        __syncthreads();
        if (tid < 512) s_pref[tid] += v;
        __syncthreads();
    }
    int nV = s_pref[ng - 1];   // inclusive scan total
    if (tid < ng) {
        int na = s_na[tid];
        int base = s_pref[tid] - na;
        for (int a = 0; a < na; a++) {
            ent_g[base + a] = (unsigned short)tid;
            ent_a[base + a] = (unsigned char)a;
            ent_s[base + a] = g_scores4[tid * 4 + a];
        }
    }
    __syncthreads();

    // sumV from deterministic partials
    float sv0 = 0.f, sv1 = 0.f;
    {
        int d0 = tid, d1 = tid + 1024;
#pragma unroll
        for (int gc = 0; gc < GCHUNKS; gc++) {
            sv0 += g_sumpart[gc * H + d0];
            sv1 += g_sumpart[gc * H + d1];
        }
    }

    // argmax (first occurrence)
    float bm = -3.4e38f; int bi = 0x7fffffff;
    for (int e = tid; e < nV; e += 1024) {
        float s = ent_s[e];
        if (s > bm || (s == bm && e < bi)) { bm = s; bi = e; }
    }
    for (int o = 16; o; o >>= 1) {
        float ov = __shfl_down_sync(0xffffffffu, bm, o);
        int oi = __shfl_down_sync(0xffffffffu, bi, o);
        if (ov > bm || (ov == bm && oi < bi)) { bm = ov; bi = oi; }
    }
    if ((tid & 31) == 0) { sred[tid >> 5] = bm; sredi[tid >> 5] = bi; }
    __syncthreads();
    if (tid == 0) {
        for (int i2 = 1; i2 < 32; i2++) {
            if (sred[i2] > sred[0] || (sred[i2] == sred[0] && sredi[i2] < sredi[0])) {
                sred[0] = sred[i2]; sredi[0] = sredi[i2];
            }
        }
    }
    __syncthreads();
    float smax = sred[0];
    int maxIdx = sredi[0];
    __syncthreads();

    // softmax denominator
    float se = 0.f;
    for (int e = tid; e < nV; e += 1024) se += expf(ent_s[e] - smax);
    se = blockRedSum(se, sred);

    // second_idx = rank of entry index 1  (np.where(np.argsort(s)==1))
    float s1 = ent_s[1];
    float cl = 0.f;
    for (int e = tid; e < nV; e += 1024) cl += (ent_s[e] < s1) ? 1.f : 0.f;
    cl = blockRedSum(cl, sred);
    int secIdx = (int)cl;
    if (secIdx >= nV) secIdx = nV - 1;

    if (tid == 0) {
        s_pnc = expf(ent_s[nc - 2] - smax) / se;
        int eg = ent_g[secIdx];
        int p2 = eg >> 3, k2 = (eg >> 1) & 3, bf2 = eg & 1;
        int i2 = pi[p2], j2 = pj[p2];
        s_sec[0] = (i2 == 2) ? -1 : (i2 < 2 ? i2 : 2 + g_comp[i2 - 3]);
        s_sec[1] = (j2 == 2) ? -1 : (j2 < 2 ? j2 : 2 + g_comp[j2 - 3]);
        s_sec[2] = k2; s_sec[3] = bf2; s_sec[4] = ent_a[secIdx];
        // comp_src update from max entry
        int mg = ent_g[maxIdx];
        int pm = mg >> 3;
        int mi = pi[pm], mj = pj[pm];
        int lc = g_ncomp;
        if (mi > 2 && mj > 2) {
            g_comp[mi - 3] = r;
            for (int t = mj - 3; t < lc - 1; t++) g_comp[t] = g_comp[t + 1];
            g_ncomp = lc - 1;
        } else if (mi <= 2 && mj > 2) {
            g_comp[mj - 3] = r;
        } else {
            g_comp[lc] = r;
            g_ncomp = lc + 1;
        }
    }
    __syncthreads();

    float pnc = s_pnc;
    int sa = s_sec[0], sb2 = s_sec[1], k2 = s_sec[2], bf2 = s_sec[3], act = s_sec[4];
    const float* pa = (sa  >= 0) ? &g_PL[(size_t)(sa  * NK + k2) * H] : nullptr;
    const float* pb = (sb2 >= 0) ? &g_PR[(size_t)(sb2 * NK + k2) * H] : nullptr;
    float gdot = 0.f, sdot = 0.f;
#pragma unroll
    for (int half = 0; half < 2; half++) {
        int d = tid + half * 1024;
        float sv = half ? sv1 : sv0;
        float gv = pnc * sv;
        g_G[r * H + d] = gv;
        out[H + r * H + d] = gv;
        if (r == 8) out[d] = gv;
        gdot = fmaf(gv, w[d], gdot);
        float a = pa ? pa[d] : 0.f;
        float c = pb ? pb[d] : 0.f;
        float bb = bv[k2 * H + d];
        float res = bf2 ? (a + c + bb) : fmaf(a, c, bb);
        float v;
        if (act == 0)      v = 0.001f / (1.f + expf(-res));
        else if (act == 1) v = 0.001f * tanhf(res);
        else if (act == 2) v = 1.f - res;
        else               v = res;
        sdot = fmaf(v, w[d], sdot);
    }
    gdot = blockRedSum(gdot, sred);
    sdot = blockRedSum(sdot, sred);
    if (tid == 0) {
        out[10 * H + r] = gdot;          // 2048 + 9*2048 = 20480
        out[10 * H + 9 + r] = sdot;
    }
}

// ---------------- host launcher ----------------
extern "C" void kernel_launch(void* const* d_in, const int* in_sizes, int n_in,
                              void* d_out, int out_size)
{
    const float* x = (const float*)d_in[0];
    const float* h = (const float*)d_in[1];
    const float* L = (const float*)d_in[2];
    const float* R = (const float*)d_in[3];
    const float* b = (const float*)d_in[4];
    const float* w = (const float*)d_in[5];
    float* out = (float*)d_out;

    k_init<<<1, 32>>>();
    k_project<<<128, 256>>>(L, R, x, h, -1);
    k_projreduce<<<128, 256>>>(0, 2);
    for (int r = 0; r < NITER; r++) {
        k_groups<<<MAXGROUPS, 256>>>(b, w, r);
        k_sumvpart<<<64, 256>>>(r);
        k_select_emit<<<1, 1024>>>(b, w, r, out);
        if (r < NITER - 1) {
            k_project<<<128, 256>>>(L, R, nullptr, nullptr, r);
            k_projreduce<<<64, 256>>>(2 + r, 1);
        }
    }
}

// round 3
// speedup vs baseline: 2.6812x; 2.6812x over previous
#include <cuda_runtime.h>
#include <math.h>

#define H      2048
#define NK     4
#define NITER  9
#define MAXSRC 11          // 0=x, 1=h, 2..10 = G[0..8]
#define MAXPAIR 64
#define MAXGROUPS 440      // C(11,2)*4*2
#define MAXENT   1760      // MAXGROUPS * 4
#define HCHUNK   32
#define GCHUNKS  8
#define GPERCHUNK 55

// ---------------- device state (no allocations allowed) ----------------
__device__ float g_PL[MAXSRC * NK * H];     // src @ L_k
__device__ float g_PR[MAXSRC * NK * H];     // src @ R_k
__device__ float g_G[NITER * H];
__device__ float g_groupsum[(size_t)MAXGROUPS * H];
__device__ float g_scores4[MAXGROUPS * 4];
__device__ int   g_aflag[MAXGROUPS];
__device__ float g_sumpart[GCHUNKS * H];
__device__ float g_projpart[(size_t)2 * 2 * NK * HCHUNK * H]; // [vec][mat][k][hc][d]
__device__ int   g_comp[16];
__device__ int   g_ncomp;

// ---------------- helpers ----------------
__device__ __forceinline__ int gen_pairs(int nc, int lc, int r,
                                         unsigned char* pi, unsigned char* pj) {
    int nri = NITER - r;
    int np = 0;
    for (int i = 0; i < nc - 1; i++)
        for (int j = i + 1; j < nc; j++) {
            bool flag;
            if (nri == lc - 1)      flag = (i >= 3);
            else if (nri == lc)     flag = (j >= 3);
            else                    flag = (nri > lc);
            if (flag) { pi[np] = (unsigned char)i; pj[np] = (unsigned char)j; np++; }
        }
    return np;
}

__device__ __forceinline__ int count_pairs(int nc, int lc, int r) {
    int nri = NITER - r;
    int np = 0;
    for (int i = 0; i < nc - 1; i++)
        for (int j = i + 1; j < nc; j++) {
            bool flag;
            if (nri == lc - 1)      flag = (i >= 3);
            else if (nri == lc)     flag = (j >= 3);
            else                    flag = (nri > lc);
            if (flag) np++;
        }
    return np;
}

__device__ __forceinline__ float blockRedSum(float v, float* s) {
    for (int o = 16; o; o >>= 1) v += __shfl_down_sync(0xffffffffu, v, o);
    int nw = blockDim.x >> 5;
    if ((threadIdx.x & 31) == 0) s[threadIdx.x >> 5] = v;
    __syncthreads();
    if (threadIdx.x == 0) {
        float r = s[0];
        for (int i = 1; i < nw; i++) r += s[i];
        s[0] = r;
    }
    __syncthreads();
    float r = s[0];
    __syncthreads();
    return r;
}

// 256-bit hinted global loads (sm_100a requires .v4.b64/.v8.b32 with L2 evict hints)
__device__ __forceinline__ void ldg8_last(const float* p, float* o) {
    unsigned long long r0, r1, r2, r3;
    asm volatile("ld.global.nc.L2::evict_last.v4.b64 {%0,%1,%2,%3},[%4];"
                 : "=l"(r0), "=l"(r1), "=l"(r2), "=l"(r3) : "l"(p));
    o[0] = __uint_as_float((unsigned)r0); o[1] = __uint_as_float((unsigned)(r0 >> 32));
    o[2] = __uint_as_float((unsigned)r1); o[3] = __uint_as_float((unsigned)(r1 >> 32));
    o[4] = __uint_as_float((unsigned)r2); o[5] = __uint_as_float((unsigned)(r2 >> 32));
    o[6] = __uint_as_float((unsigned)r3); o[7] = __uint_as_float((unsigned)(r3 >> 32));
}
__device__ __forceinline__ void ldg8_first(const float* p, float* o) {
    unsigned long long r0, r1, r2, r3;
    asm volatile("ld.global.nc.L2::evict_first.v4.b64 {%0,%1,%2,%3},[%4];"
                 : "=l"(r0), "=l"(r1), "=l"(r2), "=l"(r3) : "l"(p));
    o[0] = __uint_as_float((unsigned)r0); o[1] = __uint_as_float((unsigned)(r0 >> 32));
    o[2] = __uint_as_float((unsigned)r1); o[3] = __uint_as_float((unsigned)(r1 >> 32));
    o[4] = __uint_as_float((unsigned)r2); o[5] = __uint_as_float((unsigned)(r2 >> 32));
    o[6] = __uint_as_float((unsigned)r3); o[7] = __uint_as_float((unsigned)(r3 >> 32));
}

// ---------------- kernels ----------------
__global__ void k_init() { if (threadIdx.x == 0) g_ncomp = 0; }

// Project vector(s) through all 4 L_k and R_k.
// Grid: 2mats*4k*32hchunk = 256 blocks x 256 thr. Each block: 64 rows x full 2048 cols.
// Each thread owns 8 contiguous columns (one 32B load per row).
__global__ void __launch_bounds__(256) k_project(
    const float* __restrict__ L, const float* __restrict__ R,
    const float* __restrict__ xv, const float* __restrict__ hv, int gsrc)
{
    int bid = blockIdx.x;
    int hc   = bid & 31; bid >>= 5;
    int k    = bid & 3;  bid >>= 2;
    int mat  = bid;
    const float* M = (mat == 0 ? L : R) + (size_t)k * H * H;
    const float* v0;
    const float* v1 = nullptr;
    if (gsrc >= 0) v0 = &g_G[(size_t)gsrc * H];
    else { v0 = xv; v1 = hv; }
    const bool dual = (v1 != nullptr);

    int col = threadIdx.x * 8;
    int h0 = hc * (H / HCHUNK);                 // 64 rows per chunk
    float a0[8] = {0.f, 0.f, 0.f, 0.f, 0.f, 0.f, 0.f, 0.f};
    float a1[8] = {0.f, 0.f, 0.f, 0.f, 0.f, 0.f, 0.f, 0.f};

    if (mat == 0) {
        for (int hh = h0; hh < h0 + (H / HCHUNK); hh += 4) {
            float m[4][8];
#pragma unroll
            for (int u = 0; u < 4; u++)
                ldg8_last(&M[(size_t)(hh + u) * H + col], m[u]);
            float va[4], vb[4];
#pragma unroll
            for (int u = 0; u < 4; u++) {
                va[u] = __ldg(&v0[hh + u]);
                if (dual) vb[u] = __ldg(&v1[hh + u]);
            }
#pragma unroll
            for (int u = 0; u < 4; u++) {
#pragma unroll
                for (int e = 0; e < 8; e++) {
                    a0[e] = fmaf(va[u], m[u][e], a0[e]);
                    if (dual) a1[e] = fmaf(vb[u], m[u][e], a1[e]);
                }
            }
        }
    } else {
        for (int hh = h0; hh < h0 + (H / HCHUNK); hh += 4) {
            float m[4][8];
#pragma unroll
            for (int u = 0; u < 4; u++)
                ldg8_first(&M[(size_t)(hh + u) * H + col], m[u]);
            float va[4], vb[4];
#pragma unroll
            for (int u = 0; u < 4; u++) {
                va[u] = __ldg(&v0[hh + u]);
                if (dual) vb[u] = __ldg(&v1[hh + u]);
            }
#pragma unroll
            for (int u = 0; u < 4; u++) {
#pragma unroll
                for (int e = 0; e < 8; e++) {
                    a0[e] = fmaf(va[u], m[u][e], a0[e]);
                    if (dual) a1[e] = fmaf(vb[u], m[u][e], a1[e]);
                }
            }
        }
    }
    size_t base0 = (((size_t)(0 * 2 + mat) * NK + k) * HCHUNK + hc) * H + col;
    *reinterpret_cast<float4*>(&g_projpart[base0])     = make_float4(a0[0], a0[1], a0[2], a0[3]);
    *reinterpret_cast<float4*>(&g_projpart[base0 + 4]) = make_float4(a0[4], a0[5], a0[6], a0[7]);
    if (dual) {
        size_t base1 = (((size_t)(1 * 2 + mat) * NK + k) * HCHUNK + hc) * H + col;
        *reinterpret_cast<float4*>(&g_projpart[base1])     = make_float4(a1[0], a1[1], a1[2], a1[3]);
        *reinterpret_cast<float4*>(&g_projpart[base1 + 4]) = make_float4(a1[4], a1[5], a1[6], a1[7]);
    }
}

__global__ void __launch_bounds__(256) k_projreduce(int src0, int nvec)
{
    int idx = blockIdx.x * 256 + threadIdx.x;
    int total = nvec * 2 * NK * H;
    if (idx >= total) return;
    int d = idx & (H - 1);
    int t = idx >> 11;
    int k = t & 3;   t >>= 2;
    int mat = t & 1; t >>= 1;
    int v = t;
    float s = 0.f;
#pragma unroll
    for (int hc = 0; hc < HCHUNK; hc++)
        s += g_projpart[(((size_t)(v * 2 + mat) * NK + k) * HCHUNK + hc) * H + d];
    float* dst = (mat == 0 ? g_PL : g_PR);
    dst[((size_t)(src0 + v) * NK + k) * H + d] = s;
}

// One block per (pair,k,bf) group: res, max|res|, 4 activation scores, group act-sum vector.
// 512 threads, fused 5-way block reduction.
__global__ void __launch_bounds__(512) k_groups(
    const float* __restrict__ bv, const float* __restrict__ w, int r)
{
    __shared__ float s_res[H];
    __shared__ float s_s12[H];
    __shared__ unsigned char pi[MAXPAIR], pj[MAXPAIR];
    __shared__ int meta[6];
    __shared__ float sred[16 * 5];
    __shared__ float sbc[5];
    int tid = threadIdx.x;
    if (tid == 0) {
        int lc = g_ncomp, nc = 3 + lc;
        int np = gen_pairs(nc, lc, r, pi, pj);
        int g = blockIdx.x;
        if (g >= np * 8) meta[0] = 0;
        else {
            meta[0] = 1;
            int pidx = g >> 3, k = (g >> 1) & 3, bf = g & 1;
            int i = pi[pidx], j = pj[pidx];
            meta[1] = (i == 2) ? -1 : (i < 2 ? i : 2 + g_comp[i - 3]);
            meta[2] = (j == 2) ? -1 : (j < 2 ? j : 2 + g_comp[j - 3]);
            meta[3] = k; meta[4] = bf;
        }
    }
    __syncthreads();
    if (!meta[0]) return;
    int sa = meta[1], sbv = meta[2], k = meta[3], bf = meta[4];
    const float* pa = (sa  >= 0) ? &g_PL[(size_t)(sa  * NK + k) * H] : nullptr;
    const float* pb = (sbv >= 0) ? &g_PR[(size_t)(sbv * NK + k) * H] : nullptr;
    float am = 0.f, ds = 0.f, dt = 0.f, dm = 0.f, di = 0.f;
#pragma unroll
    for (int it = 0; it < H / 512; it++) {
        int d = tid + it * 512;
        float a = pa ? pa[d] : 0.f;
        float c = pb ? pb[d] : 0.f;
        float bb = bv[k * H + d];
        float res = bf ? (a + c + bb) : fmaf(a, c, bb);
        s_res[d] = res;
        am = fmaxf(am, fabsf(res));
        float wv = w[d];
        float sg = 0.001f * __fdividef(1.f, 1.f + __expf(-res));
        float th = 0.001f * tanhf(res);
        s_s12[d] = sg + th;
        ds = fmaf(sg, wv, ds);
        dt = fmaf(th, wv, dt);
        dm = fmaf(1.f - res, wv, dm);
        di = fmaf(res, wv, di);
    }
    // fused reduction: one warp pass + one smem pass
#pragma unroll
    for (int o = 16; o; o >>= 1) {
        am = fmaxf(am, __shfl_down_sync(0xffffffffu, am, o));
        ds += __shfl_down_sync(0xffffffffu, ds, o);
        dt += __shfl_down_sync(0xffffffffu, dt, o);
        dm += __shfl_down_sync(0xffffffffu, dm, o);
        di += __shfl_down_sync(0xffffffffu, di, o);
    }
    int wid = tid >> 5;
    if ((tid & 31) == 0) {
        sred[wid * 5 + 0] = am;
        sred[wid * 5 + 1] = ds;
        sred[wid * 5 + 2] = dt;
        sred[wid * 5 + 3] = dm;
        sred[wid * 5 + 4] = di;
    }
    __syncthreads();
    if (tid == 0) {
        float tm = sred[0], t1 = sred[1], t2 = sred[2], t3 = sred[3], t4 = sred[4];
        for (int i = 1; i < 16; i++) {
            tm = fmaxf(tm, sred[i * 5 + 0]);
            t1 += sred[i * 5 + 1];
            t2 += sred[i * 5 + 2];
            t3 += sred[i * 5 + 3];
            t4 += sred[i * 5 + 4];
        }
        int g = blockIdx.x;
        int na = (tm >= 1.0f) ? 2 : 4;
        g_aflag[g] = na;
        g_scores4[g * 4 + 0] = t1;
        g_scores4[g * 4 + 1] = t2;
        g_scores4[g * 4 + 2] = t3;
        g_scores4[g * 4 + 3] = t4;
        sbc[0] = (float)na;
    }
    __syncthreads();
    int na = (int)sbc[0];
    int g = blockIdx.x;
#pragma unroll
    for (int it = 0; it < H / 512; it++) {
        int d = tid + it * 512;
        float res = s_res[d];
        float gs = s_s12[d];
        if (na == 4) gs += (1.f - res) + res;
        g_groupsum[(size_t)g * H + d] = gs;
    }
}

// Partial (deterministic) sum of group vectors: grid 8 gchunks x 8 dblocks.
__global__ void __launch_bounds__(256) k_sumvpart(int r)
{
    int gc = blockIdx.x >> 3;
    int db = blockIdx.x & 7;
    int d = db * 256 + threadIdx.x;
    int lc = g_ncomp, nc = 3 + lc;
    int ng = count_pairs(nc, lc, r) * 8;
    int g0 = gc * GPERCHUNK;
    int g1 = min(ng, g0 + GPERCHUNK);
    float s = 0.f;
    for (int g = g0; g < g1; g++) s += g_groupsum[(size_t)g * H + d];
    g_sumpart[gc * H + d] = s;
}

// Single-block: compact entries, argmax, softmax prob[nc-2], rank-of-entry-1 second,
// comp_src update, emit G[r] / dots / outputs.
__global__ void __launch_bounds__(1024) k_select_emit(
    const float* __restrict__ bv, const float* __restrict__ w,
    int r, float* __restrict__ out)
{
    __shared__ float ent_s[MAXENT];
    __shared__ unsigned short ent_g[MAXENT];
    __shared__ unsigned char ent_a[MAXENT];
    __shared__ unsigned char pi[MAXPAIR], pj[MAXPAIR];
    __shared__ int s_na[512];
    __shared__ int s_pref[512];
    __shared__ float sred[32];
    __shared__ int sredi[32];
    __shared__ int s_ng, s_nc;
    __shared__ float s_pnc;
    __shared__ int s_sec[5];

    int tid = threadIdx.x;
    if (tid == 0) {
        int lc = g_ncomp, nc = 3 + lc;
        int np = gen_pairs(nc, lc, r, pi, pj);
        s_ng = np * 8; s_nc = nc;
    }
    __syncthreads();
    int ng = s_ng, nc = s_nc;

    if (tid < 512) s_na[tid] = (tid < ng) ? g_aflag[tid] : 0;
    __syncthreads();
    if (tid < 512) s_pref[tid] = s_na[tid];
    __syncthreads();
    for (int off = 1; off < 512; off <<= 1) {
        int v = 0;
        if (tid < 512 && tid >= off) v = s_pref[tid - off];
        __syncthreads();
        if (tid < 512) s_pref[tid] += v;
        __syncthreads();
    }
    int nV = s_pref[ng - 1];   // inclusive scan total
    if (tid < ng) {
        int na = s_na[tid];
        int base = s_pref[tid] - na;
        for (int a = 0; a < na; a++) {
            ent_g[base + a] = (unsigned short)tid;
            ent_a[base + a] = (unsigned char)a;
            ent_s[base + a] = g_scores4[tid * 4 + a];
        }
    }
    __syncthreads();

    // sumV from deterministic partials
    float sv0 = 0.f, sv1 = 0.f;
    {
        int d0 = tid, d1 = tid + 1024;
#pragma unroll
        for (int gc = 0; gc < GCHUNKS; gc++) {
            sv0 += g_sumpart[gc * H + d0];
            sv1 += g_sumpart[gc * H + d1];
        }
    }

    // argmax (first occurrence)
    float bm = -3.4e38f; int bi = 0x7fffffff;
    for (int e = tid; e < nV; e += 1024) {
        float s = ent_s[e];
        if (s > bm || (s == bm && e < bi)) { bm = s; bi = e; }
    }
    for (int o = 16; o; o >>= 1) {
        float ov = __shfl_down_sync(0xffffffffu, bm, o);
        int oi = __shfl_down_sync(0xffffffffu, bi, o);
        if (ov > bm || (ov == bm && oi < bi)) { bm = ov; bi = oi; }
    }
    if ((tid & 31) == 0) { sred[tid >> 5] = bm; sredi[tid >> 5] = bi; }
    __syncthreads();
    if (tid == 0) {
        for (int i2 = 1; i2 < 32; i2++) {
            if (sred[i2] > sred[0] || (sred[i2] == sred[0] && sredi[i2] < sredi[0])) {
                sred[0] = sred[i2]; sredi[0] = sredi[i2];
            }
        }
    }
    __syncthreads();
    float smax = sred[0];
    int maxIdx = sredi[0];
    __syncthreads();

    // softmax denominator
    float se = 0.f;
    for (int e = tid; e < nV; e += 1024) se += expf(ent_s[e] - smax);
    se = blockRedSum(se, sred);

    // second_idx = rank of entry index 1  (np.where(np.argsort(s)==1))
    float s1 = ent_s[1];
    float cl = 0.f;
    for (int e = tid; e < nV; e += 1024) cl += (ent_s[e] < s1) ? 1.f : 0.f;
    cl = blockRedSum(cl, sred);
    int secIdx = (int)cl;
    if (secIdx >= nV) secIdx = nV - 1;

    if (tid == 0) {
        s_pnc = expf(ent_s[nc - 2] - smax) / se;
        int eg = ent_g[secIdx];
        int p2 = eg >> 3, k2 = (eg >> 1) & 3, bf2 = eg & 1;
        int i2 = pi[p2], j2 = pj[p2];
        s_sec[0] = (i2 == 2) ? -1 : (i2 < 2 ? i2 : 2 + g_comp[i2 - 3]);
        s_sec[1] = (j2 == 2) ? -1 : (j2 < 2 ? j2 : 2 + g_comp[j2 - 3]);
        s_sec[2] = k2; s_sec[3] = bf2; s_sec[4] = ent_a[secIdx];
        // comp_src update from max entry
        int mg = ent_g[maxIdx];
        int pm = mg >> 3;
        int mi = pi[pm], mj = pj[pm];
        int lc = g_ncomp;
        if (mi > 2 && mj > 2) {
            g_comp[mi - 3] = r;
            for (int t = mj - 3; t < lc - 1; t++) g_comp[t] = g_comp[t + 1];
            g_ncomp = lc - 1;
        } else if (mi <= 2 && mj > 2) {
            g_comp[mj - 3] = r;
        } else {
            g_comp[lc] = r;
            g_ncomp = lc + 1;
        }
    }
    __syncthreads();

    float pnc = s_pnc;
    int sa = s_sec[0], sb2 = s_sec[1], k2 = s_sec[2], bf2 = s_sec[3], act = s_sec[4];
    const float* pa = (sa  >= 0) ? &g_PL[(size_t)(sa  * NK + k2) * H] : nullptr;
    const float* pb = (sb2 >= 0) ? &g_PR[(size_t)(sb2 * NK + k2) * H] : nullptr;
    float gdot = 0.f, sdot = 0.f;
#pragma unroll
    for (int half = 0; half < 2; half++) {
        int d = tid + half * 1024;
        float sv = half ? sv1 : sv0;
        float gv = pnc * sv;
        g_G[r * H + d] = gv;
        out[H + r * H + d] = gv;
        if (r == 8) out[d] = gv;
        gdot = fmaf(gv, w[d], gdot);
        float a = pa ? pa[d] : 0.f;
        float c = pb ? pb[d] : 0.f;
        float bb = bv[k2 * H + d];
        float res = bf2 ? (a + c + bb) : fmaf(a, c, bb);
        float v;
        if (act == 0)      v = 0.001f / (1.f + expf(-res));
        else if (act == 1) v = 0.001f * tanhf(res);
        else if (act == 2) v = 1.f - res;
        else               v = res;
        sdot = fmaf(v, w[d], sdot);
    }
    gdot = blockRedSum(gdot, sred);
    sdot = blockRedSum(sdot, sred);
    if (tid == 0) {
        out[10 * H + r] = gdot;          // 2048 + 9*2048 = 20480
        out[10 * H + 9 + r] = sdot;
    }
}

// ---------------- host launcher ----------------
extern "C" void kernel_launch(void* const* d_in, const int* in_sizes, int n_in,
                              void* d_out, int out_size)
{
    const float* x = (const float*)d_in[0];
    const float* h = (const float*)d_in[1];
    const float* L = (const float*)d_in[2];
    const float* R = (const float*)d_in[3];
    const float* b = (const float*)d_in[4];
    const float* w = (const float*)d_in[5];
    float* out = (float*)d_out;

    k_init<<<1, 32>>>();
    k_project<<<256, 256>>>(L, R, x, h, -1);
    k_projreduce<<<128, 256>>>(0, 2);
    for (int r = 0; r < NITER; r++) {
        k_groups<<<MAXGROUPS, 512>>>(b, w, r);
        k_sumvpart<<<64, 256>>>(r);
        k_select_emit<<<1, 1024>>>(b, w, r, out);
        if (r < NITER - 1) {
            k_project<<<256, 256>>>(L, R, nullptr, nullptr, r);
            k_projreduce<<<64, 256>>>(2 + r, 1);
        }
    }
}

// round 4
// speedup vs baseline: 2.9398x; 1.0964x over previous
#include <cuda_runtime.h>
#include <math.h>

#define H      2048
#define NK     4
#define NITER  9
#define MAXSRC 11          // 0=x, 1=h, 2..10 = G[0..8]
#define MAXPAIR 64
#define MAXGROUPS 440      // C(11,2)*4*2
#define MAXENT   1760      // MAXGROUPS * 4
#define HCHUNK   64
#define GCHUNKS  8
#define GPERCHUNK 55

// ---------------- device state (no allocations allowed) ----------------
__device__ float g_PL[MAXSRC * NK * H];     // src @ L_k
__device__ float g_PR[MAXSRC * NK * H];     // src @ R_k
__device__ float g_G[NITER * H];
__device__ float g_groupsum[(size_t)MAXGROUPS * H];
__device__ float g_scores4[MAXGROUPS * 4];
__device__ int   g_aflag[MAXGROUPS];
__device__ float g_sumpart[GCHUNKS * H];
__device__ float g_projpart[(size_t)2 * 2 * NK * HCHUNK * H]; // [vec][mat][k][hc][d]
__device__ int   g_comp[16];
__device__ int   g_ncomp;
__device__ int4  g_gmeta[MAXGROUPS];        // per-group {srcA, srcB, k, bf}; k=-1 invalid
__device__ int   g_ng8;

// ---------------- helpers ----------------
__device__ __forceinline__ int gen_pairs(int nc, int lc, int r,
                                         unsigned char* pi, unsigned char* pj) {
    int nri = NITER - r;
    int np = 0;
    for (int i = 0; i < nc - 1; i++)
        for (int j = i + 1; j < nc; j++) {
            bool flag;
            if (nri == lc - 1)      flag = (i >= 3);
            else if (nri == lc)     flag = (j >= 3);
            else                    flag = (nri > lc);
            if (flag) { pi[np] = (unsigned char)i; pj[np] = (unsigned char)j; np++; }
        }
    return np;
}

__device__ __forceinline__ float blockRedSum(float v, float* s) {
    for (int o = 16; o; o >>= 1) v += __shfl_down_sync(0xffffffffu, v, o);
    int nw = blockDim.x >> 5;
    if ((threadIdx.x & 31) == 0) s[threadIdx.x >> 5] = v;
    __syncthreads();
    if (threadIdx.x == 0) {
        float r = s[0];
        for (int i = 1; i < nw; i++) r += s[i];
        s[0] = r;
    }
    __syncthreads();
    float r = s[0];
    __syncthreads();
    return r;
}

__device__ __forceinline__ float tanh_fast(float x) {
    float y;
    asm("tanh.approx.f32 %0, %1;" : "=f"(y) : "f"(x));
    return y;
}

// 256-bit hinted global loads (sm_100a requires .v4.b64/.v8.b32 with L2 evict hints)
__device__ __forceinline__ void ldg8_last(const float* p, float* o) {
    unsigned long long r0, r1, r2, r3;
    asm volatile("ld.global.nc.L2::evict_last.v4.b64 {%0,%1,%2,%3},[%4];"
                 : "=l"(r0), "=l"(r1), "=l"(r2), "=l"(r3) : "l"(p));
    o[0] = __uint_as_float((unsigned)r0); o[1] = __uint_as_float((unsigned)(r0 >> 32));
    o[2] = __uint_as_float((unsigned)r1); o[3] = __uint_as_float((unsigned)(r1 >> 32));
    o[4] = __uint_as_float((unsigned)r2); o[5] = __uint_as_float((unsigned)(r2 >> 32));
    o[6] = __uint_as_float((unsigned)r3); o[7] = __uint_as_float((unsigned)(r3 >> 32));
}
__device__ __forceinline__ void ldg8_first(const float* p, float* o) {
    unsigned long long r0, r1, r2, r3;
    asm volatile("ld.global.nc.L2::evict_first.v4.b64 {%0,%1,%2,%3},[%4];"
                 : "=l"(r0), "=l"(r1), "=l"(r2), "=l"(r3) : "l"(p));
    o[0] = __uint_as_float((unsigned)r0); o[1] = __uint_as_float((unsigned)(r0 >> 32));
    o[2] = __uint_as_float((unsigned)r1); o[3] = __uint_as_float((unsigned)(r1 >> 32));
    o[4] = __uint_as_float((unsigned)r2); o[5] = __uint_as_float((unsigned)(r2 >> 32));
    o[6] = __uint_as_float((unsigned)r3); o[7] = __uint_as_float((unsigned)(r3 >> 32));
}

// ---------------- kernels ----------------
// init: ncomp=0 and round-0 group metadata (nc=3, lc=0, all 3 pairs valid)
__global__ void k_init() {
    __shared__ unsigned char qi[MAXPAIR], qj[MAXPAIR];
    __shared__ int s_np;
    int tid = threadIdx.x;
    if (tid == 0) {
        g_ncomp = 0;
        s_np = gen_pairs(3, 0, 0, qi, qj);
        g_ng8 = s_np * 8;
    }
    __syncthreads();
    int ng8 = s_np * 8;
    for (int g = tid; g < MAXGROUPS; g += blockDim.x) {
        int4 m;
        if (g < ng8) {
            int pidx = g >> 3, k = (g >> 1) & 3, bf = g & 1;
            int i = qi[pidx], j = qj[pidx];
            m.x = (i == 2) ? -1 : i;    // i<3 at round 0
            m.y = (j == 2) ? -1 : j;
            m.z = k; m.w = bf;
        } else { m.x = 0; m.y = 0; m.z = -1; m.w = 0; }
        g_gmeta[g] = m;
    }
}

// Project vector(s) through all 4 L_k and R_k.
// Grid: 2mats*4k*64hchunk = 512 blocks x 256 thr. Each block: 32 rows x full 2048 cols.
// Each thread owns 8 contiguous columns (one 32B load per row), 4 rows in flight.
__global__ void __launch_bounds__(256) k_project(
    const float* __restrict__ L, const float* __restrict__ R,
    const float* __restrict__ xv, const float* __restrict__ hv, int gsrc)
{
    int bid = blockIdx.x;
    int hc   = bid & 63; bid >>= 6;
    int k    = bid & 3;  bid >>= 2;
    int mat  = bid;
    const float* M = (mat == 0 ? L : R) + (size_t)k * H * H;
    const float* v0;
    const float* v1 = nullptr;
    if (gsrc >= 0) v0 = &g_G[(size_t)gsrc * H];
    else { v0 = xv; v1 = hv; }
    const bool dual = (v1 != nullptr);

    int col = threadIdx.x * 8;
    int h0 = hc * (H / HCHUNK);                 // 32 rows per chunk
    float a0[8] = {0.f, 0.f, 0.f, 0.f, 0.f, 0.f, 0.f, 0.f};
    float a1[8] = {0.f, 0.f, 0.f, 0.f, 0.f, 0.f, 0.f, 0.f};

    if (mat == 0) {
        for (int hh = h0; hh < h0 + (H / HCHUNK); hh += 4) {
            float m[4][8];
#pragma unroll
            for (int u = 0; u < 4; u++)
                ldg8_last(&M[(size_t)(hh + u) * H + col], m[u]);
            float va[4], vb[4];
#pragma unroll
            for (int u = 0; u < 4; u++) {
                va[u] = __ldg(&v0[hh + u]);
                if (dual) vb[u] = __ldg(&v1[hh + u]);
            }
#pragma unroll
            for (int u = 0; u < 4; u++) {
#pragma unroll
                for (int e = 0; e < 8; e++) {
                    a0[e] = fmaf(va[u], m[u][e], a0[e]);
                    if (dual) a1[e] = fmaf(vb[u], m[u][e], a1[e]);
                }
            }
        }
    } else {
        for (int hh = h0; hh < h0 + (H / HCHUNK); hh += 4) {
            float m[4][8];
#pragma unroll
            for (int u = 0; u < 4; u++)
                ldg8_first(&M[(size_t)(hh + u) * H + col], m[u]);
            float va[4], vb[4];
#pragma unroll
            for (int u = 0; u < 4; u++) {
                va[u] = __ldg(&v0[hh + u]);
                if (dual) vb[u] = __ldg(&v1[hh + u]);
            }
#pragma unroll
            for (int u = 0; u < 4; u++) {
#pragma unroll
                for (int e = 0; e < 8; e++) {
                    a0[e] = fmaf(va[u], m[u][e], a0[e]);
                    if (dual) a1[e] = fmaf(vb[u], m[u][e], a1[e]);
                }
            }
        }
    }
    size_t base0 = (((size_t)(0 * 2 + mat) * NK + k) * HCHUNK + hc) * H + col;
    *reinterpret_cast<float4*>(&g_projpart[base0])     = make_float4(a0[0], a0[1], a0[2], a0[3]);
    *reinterpret_cast<float4*>(&g_projpart[base0 + 4]) = make_float4(a0[4], a0[5], a0[6], a0[7]);
    if (dual) {
        size_t base1 = (((size_t)(1 * 2 + mat) * NK + k) * HCHUNK + hc) * H + col;
        *reinterpret_cast<float4*>(&g_projpart[base1])     = make_float4(a1[0], a1[1], a1[2], a1[3]);
        *reinterpret_cast<float4*>(&g_projpart[base1 + 4]) = make_float4(a1[4], a1[5], a1[6], a1[7]);
    }
}

__global__ void __launch_bounds__(256) k_projreduce(int src0, int nvec)
{
    int idx = blockIdx.x * 256 + threadIdx.x;
    int total = nvec * 2 * NK * H;
    if (idx >= total) return;
    int d = idx & (H - 1);
    int t = idx >> 11;
    int k = t & 3;   t >>= 2;
    int mat = t & 1; t >>= 1;
    int v = t;
    float s = 0.f;
#pragma unroll
    for (int hc = 0; hc < HCHUNK; hc++)
        s += g_projpart[(((size_t)(v * 2 + mat) * NK + k) * HCHUNK + hc) * H + d];
    float* dst = (mat == 0 ? g_PL : g_PR);
    dst[((size_t)(src0 + v) * NK + k) * H + d] = s;
}

// One block per (pair,k,bf) group: res, max|res|, 4 activation scores, group act-sum vector.
// 512 threads, metadata precomputed by previous round's select_emit.
__global__ void __launch_bounds__(512) k_groups(
    const float* __restrict__ bv, const float* __restrict__ w, int r)
{
    __shared__ float s_res[H];
    __shared__ float s_s12[H];
    __shared__ float sred[16 * 5];
    __shared__ float sbc[1];
    int4 m = __ldg(&g_gmeta[blockIdx.x]);
    if (m.z < 0) return;
    int sa = m.x, sbv = m.y, k = m.z, bf = m.w;
    int tid = threadIdx.x;
    const float* pa = (sa  >= 0) ? &g_PL[(size_t)(sa  * NK + k) * H] : nullptr;
    const float* pb = (sbv >= 0) ? &g_PR[(size_t)(sbv * NK + k) * H] : nullptr;
    float am = 0.f, ds = 0.f, dt = 0.f, dm = 0.f, di = 0.f;
#pragma unroll
    for (int it = 0; it < H / 512; it++) {
        int d = tid + it * 512;
        float a = pa ? pa[d] : 0.f;
        float c = pb ? pb[d] : 0.f;
        float bb = bv[k * H + d];
        float res = bf ? (a + c + bb) : fmaf(a, c, bb);
        s_res[d] = res;
        am = fmaxf(am, fabsf(res));
        float wv = w[d];
        float sg = 0.001f * __fdividef(1.f, 1.f + __expf(-res));
        float th = 0.001f * tanh_fast(res);
        s_s12[d] = sg + th;
        ds = fmaf(sg, wv, ds);
        dt = fmaf(th, wv, dt);
        dm = fmaf(1.f - res, wv, dm);
        di = fmaf(res, wv, di);
    }
    // fused reduction: one warp pass + one smem pass
#pragma unroll
    for (int o = 16; o; o >>= 1) {
        am = fmaxf(am, __shfl_down_sync(0xffffffffu, am, o));
        ds += __shfl_down_sync(0xffffffffu, ds, o);
        dt += __shfl_down_sync(0xffffffffu, dt, o);
        dm += __shfl_down_sync(0xffffffffu, dm, o);
        di += __shfl_down_sync(0xffffffffu, di, o);
    }
    int wid = tid >> 5;
    if ((tid & 31) == 0) {
        sred[wid * 5 + 0] = am;
        sred[wid * 5 + 1] = ds;
        sred[wid * 5 + 2] = dt;
        sred[wid * 5 + 3] = dm;
        sred[wid * 5 + 4] = di;
    }
    __syncthreads();
    if (tid == 0) {
        float tm = sred[0], t1 = sred[1], t2 = sred[2], t3 = sred[3], t4 = sred[4];
        for (int i = 1; i < 16; i++) {
            tm = fmaxf(tm, sred[i * 5 + 0]);
            t1 += sred[i * 5 + 1];
            t2 += sred[i * 5 + 2];
            t3 += sred[i * 5 + 3];
            t4 += sred[i * 5 + 4];
        }
        int g = blockIdx.x;
        int na = (tm >= 1.0f) ? 2 : 4;
        g_aflag[g] = na;
        g_scores4[g * 4 + 0] = t1;
        g_scores4[g * 4 + 1] = t2;
        g_scores4[g * 4 + 2] = t3;
        g_scores4[g * 4 + 3] = t4;
        sbc[0] = (float)na;
    }
    __syncthreads();
    int na = (int)sbc[0];
    int g = blockIdx.x;
#pragma unroll
    for (int it = 0; it < H / 512; it++) {
        int d = tid + it * 512;
        float res = s_res[d];
        float gs = s_s12[d];
        if (na == 4) gs += (1.f - res) + res;
        g_groupsum[(size_t)g * H + d] = gs;
    }
}

// Partial (deterministic) sum of group vectors: grid 8 gchunks x 8 dblocks.
__global__ void __launch_bounds__(256) k_sumvpart()
{
    int gc = blockIdx.x >> 3;
    int db = blockIdx.x & 7;
    int d = db * 256 + threadIdx.x;
    int ng = g_ng8;
    int g0 = gc * GPERCHUNK;
    int g1 = min(ng, g0 + GPERCHUNK);
    float s = 0.f;
    for (int g = g0; g < g1; g++) s += g_groupsum[(size_t)g * H + d];
    g_sumpart[gc * H + d] = s;
}

// Single-block: compact entries, argmax, softmax prob[nc-2], rank-of-entry-1 second,
// comp_src update, next-round metadata, emit G[r] / dots / outputs.
__global__ void __launch_bounds__(1024) k_select_emit(
    const float* __restrict__ bv, const float* __restrict__ w,
    int r, float* __restrict__ out)
{
    __shared__ float ent_s[MAXENT];
    __shared__ unsigned short ent_g[MAXENT];
    __shared__ unsigned char ent_a[MAXENT];
    __shared__ unsigned char pi[MAXPAIR], pj[MAXPAIR];
    __shared__ unsigned char qi[MAXPAIR], qj[MAXPAIR];
    __shared__ int s_comp[16];
    __shared__ int s_np2;
    __shared__ float sred[32];
    __shared__ int sredi[32];
    __shared__ int wsum[32];
    __shared__ int s_ng, s_nc, s_nV;
    __shared__ float s_pnc;
    __shared__ int s_sec[5];

    int tid = threadIdx.x;
    int lane = tid & 31, wid = tid >> 5;
    if (tid == 0) {
        int lc = g_ncomp, nc = 3 + lc;
        int np = gen_pairs(nc, lc, r, pi, pj);
        s_ng = np * 8; s_nc = nc;
    }
    __syncthreads();
    int ng = s_ng, nc = s_nc;

    // compact entries via warp scan over aflag (ng <= 440 < 512)
    int na = (tid < 512 && tid < ng) ? g_aflag[tid] : 0;
    {
        int v = na;
#pragma unroll
        for (int o = 1; o < 32; o <<= 1) {
            int t = __shfl_up_sync(0xffffffffu, v, o);
            if (lane >= o) v += t;
        }
        if (lane == 31) wsum[wid] = v;
        __syncthreads();
        if (wid == 0) {
            int s = wsum[lane];
#pragma unroll
            for (int o = 1; o < 32; o <<= 1) {
                int t = __shfl_up_sync(0xffffffffu, s, o);
                if (lane >= o) s += t;
            }
            wsum[lane] = s;
        }
        __syncthreads();
        int pref = v + (wid > 0 ? wsum[wid - 1] : 0);   // inclusive
        if (tid == ng - 1) s_nV = pref;
        if (tid < ng) {
            int base = pref - na;
            for (int a = 0; a < na; a++) {
                ent_g[base + a] = (unsigned short)tid;
                ent_a[base + a] = (unsigned char)a;
                ent_s[base + a] = g_scores4[tid * 4 + a];
            }
        }
    }
    __syncthreads();
    int nV = s_nV;

    // sumV from deterministic partials
    float sv0 = 0.f, sv1 = 0.f;
    {
        int d0 = tid, d1 = tid + 1024;
#pragma unroll
        for (int gc = 0; gc < GCHUNKS; gc++) {
            sv0 += g_sumpart[gc * H + d0];
            sv1 += g_sumpart[gc * H + d1];
        }
    }

    // argmax (first occurrence)
    float bm = -3.4e38f; int bi = 0x7fffffff;
    for (int e = tid; e < nV; e += 1024) {
        float s = ent_s[e];
        if (s > bm || (s == bm && e < bi)) { bm = s; bi = e; }
    }
    for (int o = 16; o; o >>= 1) {
        float ov = __shfl_down_sync(0xffffffffu, bm, o);
        int oi = __shfl_down_sync(0xffffffffu, bi, o);
        if (ov > bm || (ov == bm && oi < bi)) { bm = ov; bi = oi; }
    }
    if (lane == 0) { sred[wid] = bm; sredi[wid] = bi; }
    __syncthreads();
    if (tid == 0) {
        for (int i2 = 1; i2 < 32; i2++) {
            if (sred[i2] > sred[0] || (sred[i2] == sred[0] && sredi[i2] < sredi[0])) {
                sred[0] = sred[i2]; sredi[0] = sredi[i2];
            }
        }
    }
    __syncthreads();
    float smax = sred[0];
    int maxIdx = sredi[0];
    __syncthreads();

    // softmax denominator
    float se = 0.f;
    for (int e = tid; e < nV; e += 1024) se += expf(ent_s[e] - smax);
    se = blockRedSum(se, sred);

    // second_idx = rank of entry index 1  (np.where(np.argsort(s)==1))
    float s1 = ent_s[1];
    float cl = 0.f;
    for (int e = tid; e < nV; e += 1024) cl += (ent_s[e] < s1) ? 1.f : 0.f;
    cl = blockRedSum(cl, sred);
    int secIdx = (int)cl;
    if (secIdx >= nV) secIdx = nV - 1;

    if (tid == 0) {
        s_pnc = expf(ent_s[nc - 2] - smax) / se;
        int eg = ent_g[secIdx];
        int p2 = eg >> 3, k2 = (eg >> 1) & 3, bf2 = eg & 1;
        int i2 = pi[p2], j2 = pj[p2];
        s_sec[0] = (i2 == 2) ? -1 : (i2 < 2 ? i2 : 2 + g_comp[i2 - 3]);
        s_sec[1] = (j2 == 2) ? -1 : (j2 < 2 ? j2 : 2 + g_comp[j2 - 3]);
        s_sec[2] = k2; s_sec[3] = bf2; s_sec[4] = ent_a[secIdx];
        // comp_src update from max entry
        int mg = ent_g[maxIdx];
        int pm = mg >> 3;
        int mi = pi[pm], mj = pj[pm];
        int lc = g_ncomp;
        if (mi > 2 && mj > 2) {
            g_comp[mi - 3] = r;
            for (int t = mj - 3; t < lc - 1; t++) g_comp[t] = g_comp[t + 1];
            lc = lc - 1;
            g_ncomp = lc;
        } else if (mi <= 2 && mj > 2) {
            g_comp[mj - 3] = r;
        } else {
            g_comp[lc] = r;
            lc = lc + 1;
            g_ncomp = lc;
        }
        // prep next round: pair list + comp snapshot
        if (r < NITER - 1) {
            for (int t = 0; t < lc; t++) s_comp[t] = g_comp[t];
            s_np2 = gen_pairs(3 + lc, lc, r + 1, qi, qj);
            g_ng8 = s_np2 * 8;
        }
    }
    __syncthreads();

    // write next-round group metadata (all threads)
    if (r < NITER - 1) {
        int ng8n = s_np2 * 8;
        for (int g = tid; g < MAXGROUPS; g += 1024) {
            int4 m;
            if (g < ng8n) {
                int pidx = g >> 3, kk = (g >> 1) & 3, bff = g & 1;
                int i2 = qi[pidx], j2 = qj[pidx];
                m.x = (i2 == 2) ? -1 : (i2 < 2 ? i2 : 2 + s_comp[i2 - 3]);
                m.y = (j2 == 2) ? -1 : (j2 < 2 ? j2 : 2 + s_comp[j2 - 3]);
                m.z = kk; m.w = bff;
            } else { m.x = 0; m.y = 0; m.z = -1; m.w = 0; }
            g_gmeta[g] = m;
        }
    }

    float pnc = s_pnc;
    int sa = s_sec[0], sb2 = s_sec[1], k2 = s_sec[2], bf2 = s_sec[3], act = s_sec[4];
    const float* pa = (sa  >= 0) ? &g_PL[(size_t)(sa  * NK + k2) * H] : nullptr;
    const float* pb = (sb2 >= 0) ? &g_PR[(size_t)(sb2 * NK + k2) * H] : nullptr;
    float gdot = 0.f, sdot = 0.f;
#pragma unroll
    for (int half = 0; half < 2; half++) {
        int d = tid + half * 1024;
        float sv = half ? sv1 : sv0;
        float gv = pnc * sv;
        g_G[r * H + d] = gv;
        out[H + r * H + d] = gv;
        if (r == 8) out[d] = gv;
        gdot = fmaf(gv, w[d], gdot);
        float a = pa ? pa[d] : 0.f;
        float c = pb ? pb[d] : 0.f;
        float bb = bv[k2 * H + d];
        float res = bf2 ? (a + c + bb) : fmaf(a, c, bb);
        float v;
        if (act == 0)      v = 0.001f / (1.f + expf(-res));
        else if (act == 1) v = 0.001f * tanhf(res);
        else if (act == 2) v = 1.f - res;
        else               v = res;
        sdot = fmaf(v, w[d], sdot);
    }
    gdot = blockRedSum(gdot, sred);
    sdot = blockRedSum(sdot, sred);
    if (tid == 0) {
        out[10 * H + r] = gdot;          // 2048 + 9*2048 = 20480
        out[10 * H + 9 + r] = sdot;
    }
}

// ---------------- host launcher ----------------
extern "C" void kernel_launch(void* const* d_in, const int* in_sizes, int n_in,
                              void* d_out, int out_size)
{
    const float* x = (const float*)d_in[0];
    const float* h = (const float*)d_in[1];
    const float* L = (const float*)d_in[2];
    const float* R = (const float*)d_in[3];
    const float* b = (const float*)d_in[4];
    const float* w = (const float*)d_in[5];
    float* out = (float*)d_out;

    k_init<<<1, 256>>>();
    k_project<<<512, 256>>>(L, R, x, h, -1);
    k_projreduce<<<128, 256>>>(0, 2);
    for (int r = 0; r < NITER; r++) {
        k_groups<<<MAXGROUPS, 512>>>(b, w, r);
        k_sumvpart<<<64, 256>>>();
        k_select_emit<<<1, 1024>>>(b, w, r, out);
        if (r < NITER - 1) {
            k_project<<<512, 256>>>(L, R, nullptr, nullptr, r);
            k_projreduce<<<64, 256>>>(2 + r, 1);
        }
    }
}

// round 7
// speedup vs baseline: 3.3760x; 1.1484x over previous
#include <cuda_runtime.h>
#include <cuda_fp16.h>
#include <math.h>

#define H      2048
#define NK     4
#define NITER  9
#define MAXPAIR 64
#define MAXGROUPS 440      // C(11,2)*4*2
#define MAXENT   1760      // MAXGROUPS * 4
#define GCHUNKS  8
#define GPERCHUNK 55

// ---------------- device state (no allocations allowed) ----------------
__device__ __half g_Lh[(size_t)NK * H * H];   // fp16 shadow of L (33.5 MB)
__device__ __half g_Rh[(size_t)NK * H * H];   // fp16 shadow of R (33.5 MB)
__device__ float g_PL[11 * NK * H];           // src @ L_k   (src: 0=x,1=h,2..10=G)
__device__ float g_PR[11 * NK * H];           // src @ R_k
__device__ float g_G[NITER * H];
__device__ float g_groupsum[(size_t)MAXGROUPS * H];
__device__ float g_scores4[MAXGROUPS * 4];
__device__ int   g_aflag[MAXGROUPS];
__device__ float g_sumpart[GCHUNKS * H];
__device__ int   g_comp[16];
__device__ int   g_ncomp;
__device__ int4  g_gmeta[MAXGROUPS];          // per-group {srcA, srcB, k, bf}; k=-1 invalid
__device__ int   g_ng8;

// ---------------- helpers ----------------
__device__ __forceinline__ int gen_pairs(int nc, int lc, int r,
                                         unsigned char* pi, unsigned char* pj) {
    int nri = NITER - r;
    int np = 0;
    for (int i = 0; i < nc - 1; i++)
        for (int j = i + 1; j < nc; j++) {
            bool flag;
            if (nri == lc - 1)      flag = (i >= 3);
            else if (nri == lc)     flag = (j >= 3);
            else                    flag = (nri > lc);
            if (flag) { pi[np] = (unsigned char)i; pj[np] = (unsigned char)j; np++; }
        }
    return np;
}

__device__ __forceinline__ float blockRedSum(float v, float* s) {
    for (int o = 16; o; o >>= 1) v += __shfl_down_sync(0xffffffffu, v, o);
    int nw = blockDim.x >> 5;
    if ((threadIdx.x & 31) == 0) s[threadIdx.x >> 5] = v;
    __syncthreads();
    if (threadIdx.x == 0) {
        float r = s[0];
        for (int i = 1; i < nw; i++) r += s[i];
        s[0] = r;
    }
    __syncthreads();
    float r = s[0];
    __syncthreads();
    return r;
}

__device__ __forceinline__ float tanh_fast(float x) {
    float y;
    asm("tanh.approx.f32 %0, %1;" : "=f"(y) : "f"(x));
    return y;
}

__device__ __forceinline__ unsigned pack2h(float a, float b) {
    __half2 h = __floats2half2_rn(a, b);
    return *reinterpret_cast<unsigned*>(&h);
}

// ---------------- kernels ----------------
// init: ncomp=0 and round-0 group metadata (nc=3, lc=0, all 3 pairs valid)
__global__ void k_init() {
    __shared__ unsigned char qi[MAXPAIR], qj[MAXPAIR];
    __shared__ int s_np;
    int tid = threadIdx.x;
    if (tid == 0) {
        g_ncomp = 0;
        s_np = gen_pairs(3, 0, 0, qi, qj);
        g_ng8 = s_np * 8;
    }
    __syncthreads();
    int ng8 = s_np * 8;
    for (int g = tid; g < MAXGROUPS; g += blockDim.x) {
        int4 m;
        if (g < ng8) {
            int pidx = g >> 3, k = (g >> 1) & 3, bf = g & 1;
            int i = qi[pidx], j = qj[pidx];
            m.x = (i == 2) ? -1 : i;    // i<3 at round 0
            m.y = (j == 2) ? -1 : j;
            m.z = k; m.w = bf;
        } else { m.x = 0; m.y = 0; m.z = -1; m.w = 0; }
        g_gmeta[g] = m;
    }
}

// Convert L,R fp32 -> fp16 shadows. Stream fp32 with evict_first so the fp16
// writes (which go through L2) stay resident. 8 elems/thread.
__global__ void __launch_bounds__(256) k_convert(
    const float* __restrict__ L, const float* __restrict__ R)
{
    const size_t total = (size_t)NK * H * H;
    size_t idx = ((size_t)blockIdx.x * 256 + threadIdx.x) * 8;
    const float* src;
    __half* dst;
    if (idx < total) { src = L + idx; dst = g_Lh + idx; }
    else             { src = R + (idx - total); dst = g_Rh + (idx - total); }
    unsigned long long q0, q1, q2, q3;
    asm volatile("ld.global.nc.L2::evict_first.v4.b64 {%0,%1,%2,%3},[%4];"
                 : "=l"(q0), "=l"(q1), "=l"(q2), "=l"(q3) : "l"(src));
    uint4 o;
    o.x = pack2h(__uint_as_float((unsigned)q0), __uint_as_float((unsigned)(q0 >> 32)));
    o.y = pack2h(__uint_as_float((unsigned)q1), __uint_as_float((unsigned)(q1 >> 32)));
    o.z = pack2h(__uint_as_float((unsigned)q2), __uint_as_float((unsigned)(q2 >> 32)));
    o.w = pack2h(__uint_as_float((unsigned)q3), __uint_as_float((unsigned)(q3 >> 32)));
    *reinterpret_cast<uint4*>(dst) = o;
}

// Project vector(s) through all 4 L_k and R_k from the L2-resident fp16 shadows.
// Grid: 2mats*4k*32colblk = 256 blocks x 512 thr. Block: 64 cols x all 2048 rows.
// Thread: cg = tid&7 (8 cols), rc = tid>>3 (64 row-chunks of 32 rows).
// Intra-block smem reduction across row-chunks -> writes g_PL/g_PR directly.
__global__ void __launch_bounds__(512) k_project_h(
    const float* __restrict__ xv, const float* __restrict__ hv, int gsrc)
{
    __shared__ float part0[64][64];   // [rc][col-in-block] 16KB
    __shared__ float part1[64][64];   // dual (x,h) second vector
    int bid = blockIdx.x;
    int cb  = bid & 31; bid >>= 5;
    int k   = bid & 3;  bid >>= 2;
    int mat = bid;
    const __half* M = (mat ? g_Rh : g_Lh) + (size_t)k * H * H;
    const float* v0;
    const float* v1 = nullptr;
    if (gsrc >= 0) v0 = &g_G[(size_t)gsrc * H];
    else { v0 = xv; v1 = hv; }
    const bool dual = (v1 != nullptr);

    int tid = threadIdx.x;
    int cg = tid & 7;
    int rc = tid >> 3;
    int col = cb * 64 + cg * 8;
    int row0 = rc * 32;

    float a0[8] = {0.f, 0.f, 0.f, 0.f, 0.f, 0.f, 0.f, 0.f};
    float a1[8] = {0.f, 0.f, 0.f, 0.f, 0.f, 0.f, 0.f, 0.f};

    for (int rr = 0; rr < 32; rr += 8) {
        uint4 mv[8];
        float va[8], vb[8];
#pragma unroll
        for (int u = 0; u < 8; u++)
            mv[u] = *reinterpret_cast<const uint4*>(&M[(size_t)(row0 + rr + u) * H + col]);
#pragma unroll
        for (int u = 0; u < 8; u++) {
            va[u] = __ldg(&v0[row0 + rr + u]);
            if (dual) vb[u] = __ldg(&v1[row0 + rr + u]);
        }
#pragma unroll
        for (int u = 0; u < 8; u++) {
            const __half2* hp = reinterpret_cast<const __half2*>(&mv[u]);
            float2 f0 = __half22float2(hp[0]);
            float2 f1 = __half22float2(hp[1]);
            float2 f2 = __half22float2(hp[2]);
            float2 f3 = __half22float2(hp[3]);
            float mf[8] = {f0.x, f0.y, f1.x, f1.y, f2.x, f2.y, f3.x, f3.y};
#pragma unroll
            for (int e = 0; e < 8; e++) {
                a0[e] = fmaf(va[u], mf[e], a0[e]);
                if (dual) a1[e] = fmaf(vb[u], mf[e], a1[e]);
            }
        }
    }
#pragma unroll
    for (int e = 0; e < 8; e++) {
        part0[rc][cg * 8 + e] = a0[e];
        if (dual) part1[rc][cg * 8 + e] = a1[e];
    }
    __syncthreads();
    if (tid < 64) {
        float s0 = 0.f, s1 = 0.f;
#pragma unroll 8
        for (int r2 = 0; r2 < 64; r2++) {
            s0 += part0[r2][tid];
            if (dual) s1 += part1[r2][tid];
        }
        float* dst = mat ? g_PR : g_PL;
        int src0 = (gsrc >= 0) ? (2 + gsrc) : 0;
        dst[((size_t)src0 * NK + k) * H + cb * 64 + tid] = s0;
        if (dual) dst[((size_t)1 * NK + k) * H + cb * 64 + tid] = s1;
    }
}

// One block per (pair,k,bf) group. Register-resident (no res/s12 smem staging),
// float4 vectorized, single wave (440 blocks x 512 thr, 4 blocks/SM).
__global__ void __launch_bounds__(512) k_groups(
    const float* __restrict__ bv, const float* __restrict__ w)
{
    __shared__ float sred[16 * 5];
    __shared__ float sbc[1];
    int4 m = __ldg(&g_gmeta[blockIdx.x]);
    if (m.z < 0) return;
    int sa = m.x, sbv = m.y, k = m.z, bf = m.w;
    int tid = threadIdx.x;
    int d = tid * 4;
    float4 zero4 = make_float4(0.f, 0.f, 0.f, 0.f);
    float4 a  = (sa  >= 0) ? *reinterpret_cast<const float4*>(&g_PL[((size_t)sa  * NK + k) * H + d]) : zero4;
    float4 c  = (sbv >= 0) ? *reinterpret_cast<const float4*>(&g_PR[((size_t)sbv * NK + k) * H + d]) : zero4;
    float4 bb = *reinterpret_cast<const float4*>(&bv[k * H + d]);
    float4 wv = *reinterpret_cast<const float4*>(&w[d]);

    float res[4], s12[4];
    float ax[4] = {a.x, a.y, a.z, a.w};
    float cx[4] = {c.x, c.y, c.z, c.w};
    float bx[4] = {bb.x, bb.y, bb.z, bb.w};
    float wx[4] = {wv.x, wv.y, wv.z, wv.w};
    float am = 0.f, ds = 0.f, dt = 0.f, dm = 0.f, di = 0.f;
#pragma unroll
    for (int e = 0; e < 4; e++) {
        float r = bf ? (ax[e] + cx[e] + bx[e]) : fmaf(ax[e], cx[e], bx[e]);
        res[e] = r;
        am = fmaxf(am, fabsf(r));
        float sg = 0.001f * __fdividef(1.f, 1.f + __expf(-r));
        float th = 0.001f * tanh_fast(r);
        s12[e] = sg + th;
        ds = fmaf(sg, wx[e], ds);
        dt = fmaf(th, wx[e], dt);
        dm = fmaf(1.f - r, wx[e], dm);
        di = fmaf(r, wx[e], di);
    }
#pragma unroll
    for (int o = 16; o; o >>= 1) {
        am = fmaxf(am, __shfl_down_sync(0xffffffffu, am, o));
        ds += __shfl_down_sync(0xffffffffu, ds, o);
        dt += __shfl_down_sync(0xffffffffu, dt, o);
        dm += __shfl_down_sync(0xffffffffu, dm, o);
        di += __shfl_down_sync(0xffffffffu, di, o);
    }
    int wid = tid >> 5;
    if ((tid & 31) == 0) {
        sred[wid * 5 + 0] = am;
        sred[wid * 5 + 1] = ds;
        sred[wid * 5 + 2] = dt;
        sred[wid * 5 + 3] = dm;
        sred[wid * 5 + 4] = di;
    }
    __syncthreads();
    if (tid == 0) {
        float tm = sred[0], t1 = sred[1], t2 = sred[2], t3 = sred[3], t4 = sred[4];
        for (int i = 1; i < 16; i++) {
            tm = fmaxf(tm, sred[i * 5 + 0]);
            t1 += sred[i * 5 + 1];
            t2 += sred[i * 5 + 2];
            t3 += sred[i * 5 + 3];
            t4 += sred[i * 5 + 4];
        }
        int g = blockIdx.x;
        int na = (tm >= 1.0f) ? 2 : 4;
        g_aflag[g] = na;
        g_scores4[g * 4 + 0] = t1;
        g_scores4[g * 4 + 1] = t2;
        g_scores4[g * 4 + 2] = t3;
        g_scores4[g * 4 + 3] = t4;
        sbc[0] = (float)na;
    }
    __syncthreads();
    float addc = ((int)sbc[0] == 4) ? 1.0f : 0.0f;
    float4 o4 = make_float4(s12[0] + addc, s12[1] + addc, s12[2] + addc, s12[3] + addc);
    *reinterpret_cast<float4*>(&g_groupsum[(size_t)blockIdx.x * H + d]) = o4;
}

// Partial (deterministic) sum of group vectors: grid 8 gchunks x 8 dblocks.
__global__ void __launch_bounds__(256) k_sumvpart()
{
    int gc = blockIdx.x >> 3;
    int db = blockIdx.x & 7;
    int d = db * 256 + threadIdx.x;
    int ng = g_ng8;
    int g0 = gc * GPERCHUNK;
    int g1 = min(ng, g0 + GPERCHUNK);
    float s = 0.f;
    for (int g = g0; g < g1; g++) s += g_groupsum[(size_t)g * H + d];
    g_sumpart[gc * H + d] = s;
}

// Single-block: compact entries, argmax, softmax prob[nc-2], rank-of-entry-1 second,
// comp_src update, next-round metadata, emit G[r] / dots / outputs.
__global__ void __launch_bounds__(1024) k_select_emit(
    const float* __restrict__ bv, const float* __restrict__ w,
    int r, float* __restrict__ out)
{
    __shared__ float ent_s[MAXENT];
    __shared__ unsigned short ent_g[MAXENT];
    __shared__ unsigned char ent_a[MAXENT];
    __shared__ unsigned char pi[MAXPAIR], pj[MAXPAIR];
    __shared__ unsigned char qi[MAXPAIR], qj[MAXPAIR];
    __shared__ int s_comp[16];
    __shared__ int s_np2;
    __shared__ float sred[32];
    __shared__ int sredi[32];
    __shared__ int wsum[32];
    __shared__ int s_ng, s_nc, s_nV;
    __shared__ float s_pnc;
    __shared__ int s_sec[5];

    int tid = threadIdx.x;
    int lane = tid & 31, wid = tid >> 5;
    if (tid == 0) {
        int lc = g_ncomp, nc = 3 + lc;
        int np = gen_pairs(nc, lc, r, pi, pj);
        s_ng = np * 8; s_nc = nc;
    }
    __syncthreads();
    int ng = s_ng, nc = s_nc;

    // compact entries via warp scan over aflag (ng <= 440 < 512)
    int na = (tid < 512 && tid < ng) ? g_aflag[tid] : 0;
    {
        int v = na;
#pragma unroll
        for (int o = 1; o < 32; o <<= 1) {
            int t = __shfl_up_sync(0xffffffffu, v, o);
            if (lane >= o) v += t;
        }
        if (lane == 31) wsum[wid] = v;
        __syncthreads();
        if (wid == 0) {
            int s = wsum[lane];
#pragma unroll
            for (int o = 1; o < 32; o <<= 1) {
                int t = __shfl_up_sync(0xffffffffu, s, o);
                if (lane >= o) s += t;
            }
            wsum[lane] = s;
        }
        __syncthreads();
        int pref = v + (wid > 0 ? wsum[wid - 1] : 0);   // inclusive
        if (tid == ng - 1) s_nV = pref;
        if (tid < ng) {
            int base = pref - na;
            for (int a = 0; a < na; a++) {
                ent_g[base + a] = (unsigned short)tid;
                ent_a[base + a] = (unsigned char)a;
                ent_s[base + a] = g_scores4[tid * 4 + a];
            }
        }
    }
    __syncthreads();
    int nV = s_nV;

    // sumV from deterministic partials
    float sv0 = 0.f, sv1 = 0.f;
    {
        int d0 = tid, d1 = tid + 1024;
#pragma unroll
        for (int gc = 0; gc < GCHUNKS; gc++) {
            sv0 += g_sumpart[gc * H + d0];
            sv1 += g_sumpart[gc * H + d1];
        }
    }

    // argmax (first occurrence)
    float bm = -3.4e38f; int bi = 0x7fffffff;
    for (int e = tid; e < nV; e += 1024) {
        float s = ent_s[e];
        if (s > bm || (s == bm && e < bi)) { bm = s; bi = e; }
    }
    for (int o = 16; o; o >>= 1) {
        float ov = __shfl_down_sync(0xffffffffu, bm, o);
        int oi = __shfl_down_sync(0xffffffffu, bi, o);
        if (ov > bm || (ov == bm && oi < bi)) { bm = ov; bi = oi; }
    }
    if (lane == 0) { sred[wid] = bm; sredi[wid] = bi; }
    __syncthreads();
    if (tid == 0) {
        for (int i2 = 1; i2 < 32; i2++) {
            if (sred[i2] > sred[0] || (sred[i2] == sred[0] && sredi[i2] < sredi[0])) {
                sred[0] = sred[i2]; sredi[0] = sredi[i2];
            }
        }
    }
    __syncthreads();
    float smax = sred[0];
    int maxIdx = sredi[0];
    __syncthreads();

    // softmax denominator
    float se = 0.f;
    for (int e = tid; e < nV; e += 1024) se += expf(ent_s[e] - smax);
    se = blockRedSum(se, sred);

    // second_idx = rank of entry index 1  (np.where(np.argsort(s)==1))
    float s1 = ent_s[1];
    float cl = 0.f;
    for (int e = tid; e < nV; e += 1024) cl += (ent_s[e] < s1) ? 1.f : 0.f;
    cl = blockRedSum(cl, sred);
    int secIdx = (int)cl;
    if (secIdx >= nV) secIdx = nV - 1;

    if (tid == 0) {
        s_pnc = expf(ent_s[nc - 2] - smax) / se;
        int eg = ent_g[secIdx];
        int p2 = eg >> 3, k2 = (eg >> 1) & 3, bf2 = eg & 1;
        int i2 = pi[p2], j2 = pj[p2];
        s_sec[0] = (i2 == 2) ? -1 : (i2 < 2 ? i2 : 2 + g_comp[i2 - 3]);
        s_sec[1] = (j2 == 2) ? -1 : (j2 < 2 ? j2 : 2 + g_comp[j2 - 3]);
        s_sec[2] = k2; s_sec[3] = bf2; s_sec[4] = ent_a[secIdx];
        // comp_src update from max entry
        int mg = ent_g[maxIdx];
        int pm = mg >> 3;
        int mi = pi[pm], mj = pj[pm];
        int lc = g_ncomp;
        if (mi > 2 && mj > 2) {
            g_comp[mi - 3] = r;
            for (int t = mj - 3; t < lc - 1; t++) g_comp[t] = g_comp[t + 1];
            lc = lc - 1;
            g_ncomp = lc;
        } else if (mi <= 2 && mj > 2) {
            g_comp[mj - 3] = r;
        } else {
            g_comp[lc] = r;
            lc = lc + 1;
            g_ncomp = lc;
        }
        // prep next round: pair list + comp snapshot
        if (r < NITER - 1) {
            for (int t = 0; t < lc; t++) s_comp[t] = g_comp[t];
            s_np2 = gen_pairs(3 + lc, lc, r + 1, qi, qj);
            g_ng8 = s_np2 * 8;
        }
    }
    __syncthreads();

    // write next-round group metadata (all threads)
    if (r < NITER - 1) {
        int ng8n = s_np2 * 8;
        for (int g = tid; g < MAXGROUPS; g += 1024) {
            int4 m;
            if (g < ng8n) {
                int pidx = g >> 3, kk = (g >> 1) & 3, bff = g & 1;
                int i2 = qi[pidx], j2 = qj[pidx];
                m.x = (i2 == 2) ? -1 : (i2 < 2 ? i2 : 2 + s_comp[i2 - 3]);
                m.y = (j2 == 2) ? -1 : (j2 < 2 ? j2 : 2 + s_comp[j2 - 3]);
                m.z = kk; m.w = bff;
            } else { m.x = 0; m.y = 0; m.z = -1; m.w = 0; }
            g_gmeta[g] = m;
        }
    }

    float pnc = s_pnc;
    int sa = s_sec[0], sb2 = s_sec[1], k2 = s_sec[2], bf2 = s_sec[3], act = s_sec[4];
    const float* pa = (sa  >= 0) ? &g_PL[((size_t)sa  * NK + k2) * H] : nullptr;
    const float* pb = (sb2 >= 0) ? &g_PR[((size_t)sb2 * NK + k2) * H] : nullptr;
    float gdot = 0.f, sdot = 0.f;
#pragma unroll
    for (int half = 0; half < 2; half++) {
        int d = tid + half * 1024;
        float sv = half ? sv1 : sv0;
        float gv = pnc * sv;
        g_G[r * H + d] = gv;
        out[H + r * H + d] = gv;
        if (r == 8) out[d] = gv;
        gdot = fmaf(gv, w[d], gdot);
        float a = pa ? pa[d] : 0.f;
        float c = pb ? pb[d] : 0.f;
        float bb = bv[k2 * H + d];
        float res = bf2 ? (a + c + bb) : fmaf(a, c, bb);
        float v;
        if (act == 0)      v = 0.001f / (1.f + expf(-res));
        else if (act == 1) v = 0.001f * tanhf(res);
        else if (act == 2) v = 1.f - res;
        else               v = res;
        sdot = fmaf(v, w[d], sdot);
    }
    gdot = blockRedSum(gdot, sred);
    sdot = blockRedSum(sdot, sred);
    if (tid == 0) {
        out[10 * H + r] = gdot;          // 2048 + 9*2048 = 20480
        out[10 * H + 9 + r] = sdot;
    }
}

// ---------------- host launcher ----------------
extern "C" void kernel_launch(void* const* d_in, const int* in_sizes, int n_in,
                              void* d_out, int out_size)
{
    const float* x = (const float*)d_in[0];
    const float* h = (const float*)d_in[1];
    const float* L = (const float*)d_in[2];
    const float* R = (const float*)d_in[3];
    const float* b = (const float*)d_in[4];
    const float* w = (const float*)d_in[5];
    float* out = (float*)d_out;

    k_init<<<1, 256>>>();
    k_convert<<<16384, 256>>>(L, R);          // 2*4*2048*2048 elems / 8 per thread
    k_project_h<<<256, 512>>>(x, h, -1);
    for (int r = 0; r < NITER; r++) {
        k_groups<<<MAXGROUPS, 512>>>(b, w);
        k_sumvpart<<<64, 256>>>();
        k_select_emit<<<1, 1024>>>(b, w, r, out);
        if (r < NITER - 1) {
            k_project_h<<<256, 512>>>(nullptr, nullptr, r);
        }
    }
}